// round 9
// baseline (speedup 1.0000x reference)
#include <cuda_runtime.h>
#include <math.h>

#define Ld 2048
#define Sd 2048
#define NBd 4
#define Ed 512
#define Hd 8
#define Dd 64
#define Md (Ld * NBd)
#define BATCHd (NBd * Hd)

typedef unsigned long long u64;

// Scratch (static device globals — allocation-free per harness rules)
__device__ float g_q[(size_t)BATCHd * Ld * Dd];     // [n][h][l][d], q already +rel_u, *1/8
__device__ float g_k[(size_t)BATCHd * Sd * Dd];
__device__ float g_v[(size_t)BATCHd * Sd * Dd];
__device__ float g_sc[(size_t)BATCHd * Ld * Sd];    // scores/probs, 512 MB
__device__ float g_ao[(size_t)Md * Ed];             // attention output (L,N,E)

// ---- packed dual-fp32 FMA (sm_103a FFMA2; ptxas never auto-emits) -------
__device__ __forceinline__ u64 ffma2(u64 a, u64 b, u64 c) {
    u64 d;
    asm("fma.rn.f32x2 %0, %1, %2, %3;" : "=l"(d) : "l"(a), "l"(b), "l"(c));
    return d;
}
__device__ __forceinline__ float dlo(u64 d) { return __uint_as_float((unsigned)d); }
__device__ __forceinline__ float dhi(u64 d) { return __uint_as_float((unsigned)(d >> 32)); }

// ===========================================================================
// qk: scores[b][l][s] = sum_d q[b][l][d]*k[b][s][d]
// 256 thr (tx 0..15 over s, ty 0..15 over l-pairs), tile 128l x 128s,
// micro 4 l-pairs x 8 s. K=64 resident. 2 CTAs/SM -> 16 warps.
// ===========================================================================
#define QK_SA 132
#define QK_SB 264
__global__ void __launch_bounds__(256, 2) qk3_kernel()
{
    extern __shared__ float sm[];
    float* Qs = sm;                 // [64][QK_SA]  (k-major: [d][l])
    float* Ks = sm + 64 * QK_SA;    // [64][QK_SB]  ([d][2s dup])

    int tid = threadIdx.x;
    int s0 = blockIdx.x * 128, l0 = blockIdx.y * 128, b = blockIdx.z;
    const float* Q = g_q + (size_t)b * Ld * Dd;
    const float* K = g_k + (size_t)b * Sd * Dd;

    // load+transpose Q (128x64 -> Qs[d][l]); 512 4x4 blocks, 2/thread
    #pragma unroll
    for (int u = 0; u < 2; u++) {
        int blk = tid + u * 256;
        int d4 = (blk & 15) * 4, l4 = (blk >> 4) * 4;
        float4 r0 = *(const float4*)(Q + (size_t)(l0 + l4 + 0) * Dd + d4);
        float4 r1 = *(const float4*)(Q + (size_t)(l0 + l4 + 1) * Dd + d4);
        float4 r2 = *(const float4*)(Q + (size_t)(l0 + l4 + 2) * Dd + d4);
        float4 r3 = *(const float4*)(Q + (size_t)(l0 + l4 + 3) * Dd + d4);
        *(float4*)(Qs + (d4 + 0) * QK_SA + l4) = make_float4(r0.x, r1.x, r2.x, r3.x);
        *(float4*)(Qs + (d4 + 1) * QK_SA + l4) = make_float4(r0.y, r1.y, r2.y, r3.y);
        *(float4*)(Qs + (d4 + 2) * QK_SA + l4) = make_float4(r0.z, r1.z, r2.z, r3.z);
        *(float4*)(Qs + (d4 + 3) * QK_SA + l4) = make_float4(r0.w, r1.w, r2.w, r3.w);
    }
    // load+transpose+duplicate K (128x64 -> Ks[d][2s dup])
    #pragma unroll
    for (int u = 0; u < 2; u++) {
        int blk = tid + u * 256;
        int d4 = (blk & 15) * 4, s4 = (blk >> 4) * 4;
        float4 r0 = *(const float4*)(K + (size_t)(s0 + s4 + 0) * Dd + d4);
        float4 r1 = *(const float4*)(K + (size_t)(s0 + s4 + 1) * Dd + d4);
        float4 r2 = *(const float4*)(K + (size_t)(s0 + s4 + 2) * Dd + d4);
        float4 r3 = *(const float4*)(K + (size_t)(s0 + s4 + 3) * Dd + d4);
        float* p0 = Ks + (d4 + 0) * QK_SB + 2 * s4;
        float* p1 = Ks + (d4 + 1) * QK_SB + 2 * s4;
        float* p2 = Ks + (d4 + 2) * QK_SB + 2 * s4;
        float* p3 = Ks + (d4 + 3) * QK_SB + 2 * s4;
        *(float4*)(p0)     = make_float4(r0.x, r0.x, r1.x, r1.x);
        *(float4*)(p0 + 4) = make_float4(r2.x, r2.x, r3.x, r3.x);
        *(float4*)(p1)     = make_float4(r0.y, r0.y, r1.y, r1.y);
        *(float4*)(p1 + 4) = make_float4(r2.y, r2.y, r3.y, r3.y);
        *(float4*)(p2)     = make_float4(r0.z, r0.z, r1.z, r1.z);
        *(float4*)(p2 + 4) = make_float4(r2.z, r2.z, r3.z, r3.z);
        *(float4*)(p3)     = make_float4(r0.w, r0.w, r1.w, r1.w);
        *(float4*)(p3 + 4) = make_float4(r2.w, r2.w, r3.w, r3.w);
    }
    __syncthreads();

    int tx = tid & 15, ty = tid >> 4;
    int rb = ty * 8;                 // 4 l-pairs = 8 rows
    u64 acc[4][8] = {};

    #pragma unroll 4
    for (int k = 0; k < 64; k++) {
        const ulonglong2* Ad = (const ulonglong2*)(Qs + k * QK_SA + rb);
        u64 a[4], bb[8];
        ulonglong2 t;
        t = Ad[0]; a[0] = t.x; a[1] = t.y;
        t = Ad[1]; a[2] = t.x; a[3] = t.y;
        const u64* Bd = (const u64*)(Ks + k * QK_SB);
        const ulonglong2* B0 = (const ulonglong2*)(Bd + tx * 4);
        const ulonglong2* B1 = (const ulonglong2*)(Bd + 64 + tx * 4);
        t = B0[0]; bb[0] = t.x; bb[1] = t.y;
        t = B0[1]; bb[2] = t.x; bb[3] = t.y;
        t = B1[0]; bb[4] = t.x; bb[5] = t.y;
        t = B1[1]; bb[6] = t.x; bb[7] = t.y;
        #pragma unroll
        for (int i = 0; i < 4; i++)
            #pragma unroll
            for (int j = 0; j < 8; j++)
                acc[i][j] = ffma2(a[i], bb[j], acc[i][j]);
    }

    float* out = g_sc + (size_t)b * Ld * Sd;
    #pragma unroll
    for (int i = 0; i < 4; i++) {
        int l_lo = l0 + rb + 2 * i;
        float* r0 = out + (size_t)l_lo * Sd + s0;
        float* r1 = out + (size_t)(l_lo + 1) * Sd + s0;
        *(float4*)(r0 + tx * 4)      = make_float4(dlo(acc[i][0]), dlo(acc[i][1]), dlo(acc[i][2]), dlo(acc[i][3]));
        *(float4*)(r0 + 64 + tx * 4) = make_float4(dlo(acc[i][4]), dlo(acc[i][5]), dlo(acc[i][6]), dlo(acc[i][7]));
        *(float4*)(r1 + tx * 4)      = make_float4(dhi(acc[i][0]), dhi(acc[i][1]), dhi(acc[i][2]), dhi(acc[i][3]));
        *(float4*)(r1 + 64 + tx * 4) = make_float4(dhi(acc[i][4]), dhi(acc[i][5]), dhi(acc[i][6]), dhi(acc[i][7]));
    }
}

// ===========================================================================
// pv: out[b][l][d] = sum_s P[b][l][s]*V[b][s][d]  -> g_ao (L,N,E)
// 128 thr (tx 0..7 over d, ty 0..15 over l-pairs), tile 128l x 64d,
// k-tile 32. 4 CTAs/SM -> 16 warps. grid 512 CTAs.
// ===========================================================================
#define PV_SA 132
#define PV_SB 132
__global__ void __launch_bounds__(128, 4) pv3_kernel()
{
    extern __shared__ float sm[];
    float* Ps = sm;                 // [32][PV_SA]  ([s'][l])
    float* Vs = sm + 32 * PV_SA;    // [32][PV_SB]  ([s'][2d dup])

    int tid = threadIdx.x;
    int l0 = blockIdx.x * 128, b = blockIdx.y;
    int n = b >> 3, h = b & 7;
    const float* P = g_sc + (size_t)b * Ld * Sd;
    const float* V = g_v + (size_t)b * Sd * Dd;

    int tx = tid & 7, ty = tid >> 3;
    int rb = ty * 8;
    u64 acc[4][8] = {};

    for (int st = 0; st < Sd; st += 32) {
        __syncthreads();
        // transpose P (128x32 -> Ps[s'][l]); 256 4x4 blocks, 2/thread
        #pragma unroll
        for (int u = 0; u < 2; u++) {
            int blk = tid + u * 128;
            int s4 = (blk & 7) * 4, m4 = (blk >> 3) * 4;
            float4 r0 = *(const float4*)(P + (size_t)(l0 + m4 + 0) * Sd + st + s4);
            float4 r1 = *(const float4*)(P + (size_t)(l0 + m4 + 1) * Sd + st + s4);
            float4 r2 = *(const float4*)(P + (size_t)(l0 + m4 + 2) * Sd + st + s4);
            float4 r3 = *(const float4*)(P + (size_t)(l0 + m4 + 3) * Sd + st + s4);
            *(float4*)(Ps + (s4 + 0) * PV_SA + m4) = make_float4(r0.x, r1.x, r2.x, r3.x);
            *(float4*)(Ps + (s4 + 1) * PV_SA + m4) = make_float4(r0.y, r1.y, r2.y, r3.y);
            *(float4*)(Ps + (s4 + 2) * PV_SA + m4) = make_float4(r0.z, r1.z, r2.z, r3.z);
            *(float4*)(Ps + (s4 + 3) * PV_SA + m4) = make_float4(r0.w, r1.w, r2.w, r3.w);
        }
        // V duplicated (32x64 -> Vs[s'][2d dup]); 512 float4, 4/thread
        #pragma unroll
        for (int u = 0; u < 4; u++) {
            int idx = tid + u * 128;
            int d4 = (idx & 15) * 4, r = idx >> 4;
            float4 v = *(const float4*)(V + (size_t)(st + r) * Dd + d4);
            *(float4*)(Vs + r * PV_SB + 2 * d4)     = make_float4(v.x, v.x, v.y, v.y);
            *(float4*)(Vs + r * PV_SB + 2 * d4 + 4) = make_float4(v.z, v.z, v.w, v.w);
        }
        __syncthreads();

        #pragma unroll 4
        for (int k = 0; k < 32; k++) {
            const ulonglong2* Ad = (const ulonglong2*)(Ps + k * PV_SA + rb);
            u64 a[4], bb[8];
            ulonglong2 t;
            t = Ad[0]; a[0] = t.x; a[1] = t.y;
            t = Ad[1]; a[2] = t.x; a[3] = t.y;
            const u64* Bd = (const u64*)(Vs + k * PV_SB);
            const ulonglong2* B0 = (const ulonglong2*)(Bd + tx * 4);
            const ulonglong2* B1 = (const ulonglong2*)(Bd + 32 + tx * 4);
            t = B0[0]; bb[0] = t.x; bb[1] = t.y;
            t = B0[1]; bb[2] = t.x; bb[3] = t.y;
            t = B1[0]; bb[4] = t.x; bb[5] = t.y;
            t = B1[1]; bb[6] = t.x; bb[7] = t.y;
            #pragma unroll
            for (int i = 0; i < 4; i++)
                #pragma unroll
                for (int j = 0; j < 8; j++)
                    acc[i][j] = ffma2(a[i], bb[j], acc[i][j]);
        }
    }

    #pragma unroll
    for (int i = 0; i < 4; i++) {
        int l_lo = l0 + rb + 2 * i;
        float* r0 = g_ao + ((size_t)l_lo * NBd + n) * Ed + h * Dd;
        float* r1 = g_ao + ((size_t)(l_lo + 1) * NBd + n) * Ed + h * Dd;
        *(float4*)(r0 + tx * 4)      = make_float4(dlo(acc[i][0]), dlo(acc[i][1]), dlo(acc[i][2]), dlo(acc[i][3]));
        *(float4*)(r0 + 32 + tx * 4) = make_float4(dlo(acc[i][4]), dlo(acc[i][5]), dlo(acc[i][6]), dlo(acc[i][7]));
        *(float4*)(r1 + tx * 4)      = make_float4(dhi(acc[i][0]), dhi(acc[i][1]), dhi(acc[i][2]), dhi(acc[i][3]));
        *(float4*)(r1 + 32 + tx * 4) = make_float4(dhi(acc[i][4]), dhi(acc[i][5]), dhi(acc[i][6]), dhi(acc[i][7]));
    }
}

// ===========================================================================
// proj: Y = X @ W^T + bias (optionally +rel, *scale)
// 128 thr, tile 128m x 64e, k-tile 32, K=512. 4 CTAs/SM. grid 512 CTAs.
// mode 0/1/2 -> scatter to g_q/g_k/g_v as [n][h][l][d]; mode 3 -> plain out.
// ===========================================================================
#define PJ_SA 132
#define PJ_SB 132
__global__ void __launch_bounds__(128, 4) proj3_kernel(
    const float* __restrict__ X, const float* __restrict__ W,
    const float* __restrict__ bias, const float* __restrict__ rel,
    float scale, int mode, float* __restrict__ outp)
{
    extern __shared__ float sm[];
    float* Xs = sm;                 // [32][PJ_SA]
    float* Ws = sm + 32 * PJ_SA;    // [32][PJ_SB] (dup)
    const float* Xp = (mode == 3) ? (const float*)g_ao : X;

    int tid = threadIdx.x;
    int e0 = blockIdx.x * 64, m0 = blockIdx.y * 128;
    int tx = tid & 7, ty = tid >> 3;
    int rb = ty * 8;
    u64 acc[4][8] = {};

    for (int kt = 0; kt < Ed; kt += 32) {
        __syncthreads();
        // transpose X (128x32 -> Xs[k'][m]); 2 blocks/thread
        #pragma unroll
        for (int u = 0; u < 2; u++) {
            int blk = tid + u * 128;
            int k4 = (blk & 7) * 4, m4 = (blk >> 3) * 4;
            float4 r0 = *(const float4*)(Xp + (size_t)(m0 + m4 + 0) * Ed + kt + k4);
            float4 r1 = *(const float4*)(Xp + (size_t)(m0 + m4 + 1) * Ed + kt + k4);
            float4 r2 = *(const float4*)(Xp + (size_t)(m0 + m4 + 2) * Ed + kt + k4);
            float4 r3 = *(const float4*)(Xp + (size_t)(m0 + m4 + 3) * Ed + kt + k4);
            *(float4*)(Xs + (k4 + 0) * PJ_SA + m4) = make_float4(r0.x, r1.x, r2.x, r3.x);
            *(float4*)(Xs + (k4 + 1) * PJ_SA + m4) = make_float4(r0.y, r1.y, r2.y, r3.y);
            *(float4*)(Xs + (k4 + 2) * PJ_SA + m4) = make_float4(r0.z, r1.z, r2.z, r3.z);
            *(float4*)(Xs + (k4 + 3) * PJ_SA + m4) = make_float4(r0.w, r1.w, r2.w, r3.w);
        }
        // transpose+duplicate W (64x32 -> Ws[k'][2e dup]); 1 block/thread
        {
            int k4 = (tid & 7) * 4, e4 = (tid >> 3) * 4;
            float4 w0 = *(const float4*)(W + (size_t)(e0 + e4 + 0) * Ed + kt + k4);
            float4 w1 = *(const float4*)(W + (size_t)(e0 + e4 + 1) * Ed + kt + k4);
            float4 w2 = *(const float4*)(W + (size_t)(e0 + e4 + 2) * Ed + kt + k4);
            float4 w3 = *(const float4*)(W + (size_t)(e0 + e4 + 3) * Ed + kt + k4);
            float* p0 = Ws + (k4 + 0) * PJ_SB + 2 * e4;
            float* p1 = Ws + (k4 + 1) * PJ_SB + 2 * e4;
            float* p2 = Ws + (k4 + 2) * PJ_SB + 2 * e4;
            float* p3 = Ws + (k4 + 3) * PJ_SB + 2 * e4;
            *(float4*)(p0)     = make_float4(w0.x, w0.x, w1.x, w1.x);
            *(float4*)(p0 + 4) = make_float4(w2.x, w2.x, w3.x, w3.x);
            *(float4*)(p1)     = make_float4(w0.y, w0.y, w1.y, w1.y);
            *(float4*)(p1 + 4) = make_float4(w2.y, w2.y, w3.y, w3.y);
            *(float4*)(p2)     = make_float4(w0.z, w0.z, w1.z, w1.z);
            *(float4*)(p2 + 4) = make_float4(w2.z, w2.z, w3.z, w3.z);
            *(float4*)(p3)     = make_float4(w0.w, w0.w, w1.w, w1.w);
            *(float4*)(p3 + 4) = make_float4(w2.w, w2.w, w3.w, w3.w);
        }
        __syncthreads();

        #pragma unroll 4
        for (int k = 0; k < 32; k++) {
            const ulonglong2* Ad = (const ulonglong2*)(Xs + k * PJ_SA + rb);
            u64 a[4], bb[8];
            ulonglong2 t;
            t = Ad[0]; a[0] = t.x; a[1] = t.y;
            t = Ad[1]; a[2] = t.x; a[3] = t.y;
            const u64* Bd = (const u64*)(Ws + k * PJ_SB);
            const ulonglong2* B0 = (const ulonglong2*)(Bd + tx * 4);
            const ulonglong2* B1 = (const ulonglong2*)(Bd + 32 + tx * 4);
            t = B0[0]; bb[0] = t.x; bb[1] = t.y;
            t = B0[1]; bb[2] = t.x; bb[3] = t.y;
            t = B1[0]; bb[4] = t.x; bb[5] = t.y;
            t = B1[1]; bb[6] = t.x; bb[7] = t.y;
            #pragma unroll
            for (int i = 0; i < 4; i++)
                #pragma unroll
                for (int j = 0; j < 8; j++)
                    acc[i][j] = ffma2(a[i], bb[j], acc[i][j]);
        }
    }

    // epilogue
    float bs[8], rl[8];
    #pragma unroll
    for (int jj = 0; jj < 4; jj++) {
        int ea = e0 + tx * 4 + jj, eb2 = e0 + 32 + tx * 4 + jj;
        bs[jj] = bias[ea];     bs[4 + jj] = bias[eb2];
        rl[jj] = rel ? rel[ea] : 0.f;
        rl[4 + jj] = rel ? rel[eb2] : 0.f;
    }
    int hh = e0 >> 6;
    float* dst012 = (mode == 0) ? g_q : (mode == 1) ? g_k : g_v;

    #pragma unroll
    for (int i = 0; i < 4; i++) {
        #pragma unroll
        for (int hp = 0; hp < 2; hp++) {
            int m = m0 + rb + 2 * i + hp;
            float v[8];
            #pragma unroll
            for (int j = 0; j < 8; j++) {
                float x = hp ? dhi(acc[i][j]) : dlo(acc[i][j]);
                v[j] = (x + bs[j] + rl[j]) * scale;
            }
            if (mode < 3) {
                int l = m >> 2, nn = m & 3;
                float* base = dst012 + ((size_t)(nn * Hd + hh) * Ld + l) * Dd;
                *(float4*)(base + tx * 4)      = make_float4(v[0], v[1], v[2], v[3]);
                *(float4*)(base + 32 + tx * 4) = make_float4(v[4], v[5], v[6], v[7]);
            } else {
                float* base = outp + (size_t)m * Ed + e0;
                *(float4*)(base + tx * 4)      = make_float4(v[0], v[1], v[2], v[3]);
                *(float4*)(base + 32 + tx * 4) = make_float4(v[4], v[5], v[6], v[7]);
            }
        }
    }
}

// ===========================================================================
// Softmax in place over s (per l,n,h) + head-mean -> att_weights
// ===========================================================================
__global__ void __launch_bounds__(256) softmax_kernel(float* __restrict__ attw)
{
    int l = blockIdx.x, n = blockIdx.y;
    int tid = threadIdx.x;
    __shared__ float red[8];
    float mean[8] = {0, 0, 0, 0, 0, 0, 0, 0};

    for (int h = 0; h < Hd; h++) {
        float* row = g_sc + ((size_t)(n * Hd + h) * Ld + l) * Sd;
        float x[8];
        float mx = -1e30f;
        #pragma unroll
        for (int i = 0; i < 8; i++) {
            x[i] = row[tid + (i << 8)];
            mx = fmaxf(mx, x[i]);
        }
        #pragma unroll
        for (int o = 16; o; o >>= 1) mx = fmaxf(mx, __shfl_xor_sync(0xffffffffu, mx, o));
        if ((tid & 31) == 0) red[tid >> 5] = mx;
        __syncthreads();
        if (tid < 32) {
            float w = (tid < 8) ? red[tid] : -1e30f;
            #pragma unroll
            for (int o = 4; o; o >>= 1) w = fmaxf(w, __shfl_xor_sync(0xffffffffu, w, o));
            if (tid == 0) red[0] = w;
        }
        __syncthreads();
        mx = red[0];
        __syncthreads();

        float sum = 0.f;
        #pragma unroll
        for (int i = 0; i < 8; i++) {
            x[i] = __expf(x[i] - mx);
            sum += x[i];
        }
        #pragma unroll
        for (int o = 16; o; o >>= 1) sum += __shfl_xor_sync(0xffffffffu, sum, o);
        if ((tid & 31) == 0) red[tid >> 5] = sum;
        __syncthreads();
        if (tid < 32) {
            float w = (tid < 8) ? red[tid] : 0.f;
            #pragma unroll
            for (int o = 4; o; o >>= 1) w += __shfl_xor_sync(0xffffffffu, w, o);
            if (tid == 0) red[0] = w;
        }
        __syncthreads();
        float inv = 1.0f / red[0];
        __syncthreads();

        #pragma unroll
        for (int i = 0; i < 8; i++) {
            float p = x[i] * inv;
            row[tid + (i << 8)] = p;
            mean[i] += p;
        }
    }

    float* aw = attw + ((size_t)n * Ld + l) * Sd;
    #pragma unroll
    for (int i = 0; i < 8; i++)
        aw[tid + (i << 8)] = mean[i] * 0.125f;
}

// ---------------------------------------------------------------------------
extern "C" void kernel_launch(void* const* d_in, const int* in_sizes, int n_in,
                              void* d_out, int out_size)
{
    const float* query = (const float*)d_in[0];
    const float* key   = (const float*)d_in[1];
    const float* value = (const float*)d_in[2];
    // d_in[3] sin_pos_enc: unused — rel_shift term is constant over the
    // softmax axis in the reference and cancels exactly.
    const float* W     = (const float*)d_in[4];   // (3E, E)
    const float* bias  = (const float*)d_in[5];   // (3E,)
    const float* out_w = (const float*)d_in[6];
    const float* out_b = (const float*)d_in[7];
    // d_in[8] rel_proj_w: unused (cancels)
    const float* rel_u = (const float*)d_in[9];   // (H,D) == E contiguous floats
    // d_in[10] rel_v: unused (cancels)

    float* out  = (float*)d_out;                      // (L, N, E)
    float* attw = out + (size_t)Ld * NBd * Ed;        // (N, L, S)

    const int QK_SMEM = (64 * QK_SA + 64 * QK_SB) * 4;   // 101376 B
    const int PV_SMEM = (32 * PV_SA + 32 * PV_SB) * 4;   // 33792 B
    const int PJ_SMEM = (32 * PJ_SA + 32 * PJ_SB) * 4;   // 33792 B
    cudaFuncSetAttribute(qk3_kernel,   cudaFuncAttributeMaxDynamicSharedMemorySize, QK_SMEM);
    cudaFuncSetAttribute(pv3_kernel,   cudaFuncAttributeMaxDynamicSharedMemorySize, PV_SMEM);
    cudaFuncSetAttribute(proj3_kernel, cudaFuncAttributeMaxDynamicSharedMemorySize, PJ_SMEM);

    dim3 gp(Ed / 64, Md / 128);
    // q_eff = (q + rel_u) / sqrt(D)
    proj3_kernel<<<gp, 128, PJ_SMEM>>>(query, W,               bias,          rel_u,   0.125f, 0, nullptr);
    proj3_kernel<<<gp, 128, PJ_SMEM>>>(key,   W + Ed * Ed,     bias + Ed,     nullptr, 1.0f,   1, nullptr);
    proj3_kernel<<<gp, 128, PJ_SMEM>>>(value, W + 2 * Ed * Ed, bias + 2 * Ed, nullptr, 1.0f,   2, nullptr);

    qk3_kernel<<<dim3(Sd / 128, Ld / 128, BATCHd), 256, QK_SMEM>>>();
    softmax_kernel<<<dim3(Ld, NBd), 256>>>(attw);
    pv3_kernel<<<dim3(Ld / 128, BATCHd), 128, PV_SMEM>>>();

    proj3_kernel<<<gp, 128, PJ_SMEM>>>(nullptr, out_w, out_b, nullptr, 1.0f, 3, out);
}

// round 10
// speedup vs baseline: 1.6567x; 1.6567x over previous
#include <cuda_runtime.h>
#include <math.h>

#define Ld 2048
#define Sd 2048
#define NBd 4
#define Ed 512
#define Hd 8
#define Dd 64
#define Md (Ld * NBd)
#define BATCHd (NBd * Hd)

typedef unsigned long long u64;

// Scratch (static device globals — allocation-free per harness rules)
__device__ float g_q[(size_t)BATCHd * Ld * Dd];     // [n][h][l][d], q already +rel_u, *1/8
__device__ float g_k[(size_t)BATCHd * Sd * Dd];
__device__ float g_v[(size_t)BATCHd * Sd * Dd];
__device__ float g_sc[(size_t)BATCHd * Ld * Sd];    // scores/probs, 512 MB
__device__ float g_ao[(size_t)Md * Ed];             // attention output (L,N,E)

// ---- packed dual-fp32 FMA (sm_103a FFMA2; ptxas never auto-emits) -------
__device__ __forceinline__ u64 ffma2(u64 a, u64 b, u64 c) {
    u64 d;
    asm("fma.rn.f32x2 %0, %1, %2, %3;" : "=l"(d) : "l"(a), "l"(b), "l"(c));
    return d;
}
__device__ __forceinline__ float dlo(u64 d) { return __uint_as_float((unsigned)d); }
__device__ __forceinline__ float dhi(u64 d) { return __uint_as_float((unsigned)(d >> 32)); }
// duplicate one fp32 into both lanes of a 64-bit pair (1 ALU op, off the fma pipe)
__device__ __forceinline__ u64 dup2(float f) {
    u64 d; unsigned b = __float_as_uint(f);
    asm("mov.b64 %0, {%1, %1};" : "=l"(d) : "r"(b));
    return d;
}

// ===========================================================================
// qk: scores[b][l][s] = sum_d q[b][l][d]*k[b][s][d]
// 128 thr (tx 0..15 over s*8, ty 0..7 over 8 l-pairs), tile 128l x 128s,
// K=64 resident. B natural in smem; dup built in regs.
// ===========================================================================
#define QK_SA 132
#define QK_SB 132
__global__ void __launch_bounds__(128, 2) qk4_kernel()
{
    extern __shared__ float sm[];
    float* Qs = sm;                 // [64][132]  ([d][l])
    float* Ks = sm + 64 * QK_SA;    // [64][132]  ([d][s], natural)

    int tid = threadIdx.x;
    int s0 = blockIdx.x * 128, l0 = blockIdx.y * 128, b = blockIdx.z;
    const float* Q = g_q + (size_t)b * Ld * Dd;
    const float* K = g_k + (size_t)b * Sd * Dd;

    // load+transpose Q (128x64 -> Qs[d][l]); 512 4x4 blocks, 4/thread
    #pragma unroll
    for (int u = 0; u < 4; u++) {
        int blk = tid + u * 128;
        int d4 = (blk & 15) * 4, l4 = (blk >> 4) * 4;
        float4 r0 = *(const float4*)(Q + (size_t)(l0 + l4 + 0) * Dd + d4);
        float4 r1 = *(const float4*)(Q + (size_t)(l0 + l4 + 1) * Dd + d4);
        float4 r2 = *(const float4*)(Q + (size_t)(l0 + l4 + 2) * Dd + d4);
        float4 r3 = *(const float4*)(Q + (size_t)(l0 + l4 + 3) * Dd + d4);
        *(float4*)(Qs + (d4 + 0) * QK_SA + l4) = make_float4(r0.x, r1.x, r2.x, r3.x);
        *(float4*)(Qs + (d4 + 1) * QK_SA + l4) = make_float4(r0.y, r1.y, r2.y, r3.y);
        *(float4*)(Qs + (d4 + 2) * QK_SA + l4) = make_float4(r0.z, r1.z, r2.z, r3.z);
        *(float4*)(Qs + (d4 + 3) * QK_SA + l4) = make_float4(r0.w, r1.w, r2.w, r3.w);
    }
    // load+transpose K (128x64 -> Ks[d][s], natural)
    #pragma unroll
    for (int u = 0; u < 4; u++) {
        int blk = tid + u * 128;
        int d4 = (blk & 15) * 4, s4 = (blk >> 4) * 4;
        float4 r0 = *(const float4*)(K + (size_t)(s0 + s4 + 0) * Dd + d4);
        float4 r1 = *(const float4*)(K + (size_t)(s0 + s4 + 1) * Dd + d4);
        float4 r2 = *(const float4*)(K + (size_t)(s0 + s4 + 2) * Dd + d4);
        float4 r3 = *(const float4*)(K + (size_t)(s0 + s4 + 3) * Dd + d4);
        *(float4*)(Ks + (d4 + 0) * QK_SB + s4) = make_float4(r0.x, r1.x, r2.x, r3.x);
        *(float4*)(Ks + (d4 + 1) * QK_SB + s4) = make_float4(r0.y, r1.y, r2.y, r3.y);
        *(float4*)(Ks + (d4 + 2) * QK_SB + s4) = make_float4(r0.z, r1.z, r2.z, r3.z);
        *(float4*)(Ks + (d4 + 3) * QK_SB + s4) = make_float4(r0.w, r1.w, r2.w, r3.w);
    }
    __syncthreads();

    int tx = tid & 15, ty = tid >> 4;
    int rb = ty * 16;                // 8 l-pairs = 16 rows
    u64 acc[8][8] = {};

    #pragma unroll 4
    for (int k = 0; k < 64; k++) {
        const ulonglong2* Ad = (const ulonglong2*)(Qs + k * QK_SA + rb);
        u64 a[8], bb[8];
        ulonglong2 t;
        t = Ad[0]; a[0] = t.x; a[1] = t.y;
        t = Ad[1]; a[2] = t.x; a[3] = t.y;
        t = Ad[2]; a[4] = t.x; a[5] = t.y;
        t = Ad[3]; a[6] = t.x; a[7] = t.y;
        const float4* Bf = (const float4*)(Ks + k * QK_SB + tx * 8);
        float4 b0 = Bf[0], b1 = Bf[1];
        bb[0] = dup2(b0.x); bb[1] = dup2(b0.y); bb[2] = dup2(b0.z); bb[3] = dup2(b0.w);
        bb[4] = dup2(b1.x); bb[5] = dup2(b1.y); bb[6] = dup2(b1.z); bb[7] = dup2(b1.w);
        #pragma unroll
        for (int i = 0; i < 8; i++)
            #pragma unroll
            for (int j = 0; j < 8; j++)
                acc[i][j] = ffma2(a[i], bb[j], acc[i][j]);
    }

    float* out = g_sc + (size_t)b * Ld * Sd;
    #pragma unroll
    for (int i = 0; i < 8; i++) {
        int l_lo = l0 + rb + 2 * i;
        float* r0 = out + (size_t)l_lo * Sd + s0 + tx * 8;
        float* r1 = out + (size_t)(l_lo + 1) * Sd + s0 + tx * 8;
        *(float4*)(r0)     = make_float4(dlo(acc[i][0]), dlo(acc[i][1]), dlo(acc[i][2]), dlo(acc[i][3]));
        *(float4*)(r0 + 4) = make_float4(dlo(acc[i][4]), dlo(acc[i][5]), dlo(acc[i][6]), dlo(acc[i][7]));
        *(float4*)(r1)     = make_float4(dhi(acc[i][0]), dhi(acc[i][1]), dhi(acc[i][2]), dhi(acc[i][3]));
        *(float4*)(r1 + 4) = make_float4(dhi(acc[i][4]), dhi(acc[i][5]), dhi(acc[i][6]), dhi(acc[i][7]));
    }
}

// ===========================================================================
// pv: out[b][l][d] = sum_s P[b][l][s]*V[b][s][d]  -> g_ao (L,N,E)
// 128 thr (tx 0..7 over d*8, ty 0..15 over 8 l-pairs), tile 256l x 64d,
// k-tile 32. B natural; dup in regs.
// ===========================================================================
#define PV_SA 260
#define PV_SB 68
__global__ void __launch_bounds__(128, 2) pv4_kernel()
{
    extern __shared__ float sm[];
    float* Ps = sm;                 // [32][260]  ([s'][l])
    float* Vs = sm + 32 * PV_SA;    // [32][68]   ([s'][d], natural)

    int tid = threadIdx.x;
    int l0 = blockIdx.x * 256, b = blockIdx.y;
    int n = b >> 3, h = b & 7;
    const float* P = g_sc + (size_t)b * Ld * Sd;
    const float* V = g_v + (size_t)b * Sd * Dd;

    int tx = tid & 7, ty = tid >> 3;
    int rb = ty * 16;
    u64 acc[8][8] = {};

    for (int st = 0; st < Sd; st += 32) {
        __syncthreads();
        // transpose P (256x32 -> Ps[s'][l]); 512 4x4 blocks, 4/thread
        #pragma unroll
        for (int u = 0; u < 4; u++) {
            int blk = tid + u * 128;
            int s4 = (blk & 7) * 4, m4 = (blk >> 3) * 4;
            float4 r0 = *(const float4*)(P + (size_t)(l0 + m4 + 0) * Sd + st + s4);
            float4 r1 = *(const float4*)(P + (size_t)(l0 + m4 + 1) * Sd + st + s4);
            float4 r2 = *(const float4*)(P + (size_t)(l0 + m4 + 2) * Sd + st + s4);
            float4 r3 = *(const float4*)(P + (size_t)(l0 + m4 + 3) * Sd + st + s4);
            *(float4*)(Ps + (s4 + 0) * PV_SA + m4) = make_float4(r0.x, r1.x, r2.x, r3.x);
            *(float4*)(Ps + (s4 + 1) * PV_SA + m4) = make_float4(r0.y, r1.y, r2.y, r3.y);
            *(float4*)(Ps + (s4 + 2) * PV_SA + m4) = make_float4(r0.z, r1.z, r2.z, r3.z);
            *(float4*)(Ps + (s4 + 3) * PV_SA + m4) = make_float4(r0.w, r1.w, r2.w, r3.w);
        }
        // copy V (32x64 -> Vs natural); 512 float4, 4/thread
        #pragma unroll
        for (int u = 0; u < 4; u++) {
            int idx = tid + u * 128;
            int d4 = (idx & 15) * 4, r = idx >> 4;
            *(float4*)(Vs + r * PV_SB + d4) = *(const float4*)(V + (size_t)(st + r) * Dd + d4);
        }
        __syncthreads();

        #pragma unroll 4
        for (int k = 0; k < 32; k++) {
            const ulonglong2* Ad = (const ulonglong2*)(Ps + k * PV_SA + rb);
            u64 a[8], bb[8];
            ulonglong2 t;
            t = Ad[0]; a[0] = t.x; a[1] = t.y;
            t = Ad[1]; a[2] = t.x; a[3] = t.y;
            t = Ad[2]; a[4] = t.x; a[5] = t.y;
            t = Ad[3]; a[6] = t.x; a[7] = t.y;
            const float4* Bf = (const float4*)(Vs + k * PV_SB + tx * 8);
            float4 b0 = Bf[0], b1 = Bf[1];
            bb[0] = dup2(b0.x); bb[1] = dup2(b0.y); bb[2] = dup2(b0.z); bb[3] = dup2(b0.w);
            bb[4] = dup2(b1.x); bb[5] = dup2(b1.y); bb[6] = dup2(b1.z); bb[7] = dup2(b1.w);
            #pragma unroll
            for (int i = 0; i < 8; i++)
                #pragma unroll
                for (int j = 0; j < 8; j++)
                    acc[i][j] = ffma2(a[i], bb[j], acc[i][j]);
        }
    }

    #pragma unroll
    for (int i = 0; i < 8; i++) {
        int l_lo = l0 + rb + 2 * i;
        float* r0 = g_ao + ((size_t)l_lo * NBd + n) * Ed + h * Dd + tx * 8;
        float* r1 = g_ao + ((size_t)(l_lo + 1) * NBd + n) * Ed + h * Dd + tx * 8;
        *(float4*)(r0)     = make_float4(dlo(acc[i][0]), dlo(acc[i][1]), dlo(acc[i][2]), dlo(acc[i][3]));
        *(float4*)(r0 + 4) = make_float4(dlo(acc[i][4]), dlo(acc[i][5]), dlo(acc[i][6]), dlo(acc[i][7]));
        *(float4*)(r1)     = make_float4(dhi(acc[i][0]), dhi(acc[i][1]), dhi(acc[i][2]), dhi(acc[i][3]));
        *(float4*)(r1 + 4) = make_float4(dhi(acc[i][4]), dhi(acc[i][5]), dhi(acc[i][6]), dhi(acc[i][7]));
    }
}

// ===========================================================================
// proj: Y = X @ W^T + bias (optionally +rel, *scale)
// 128 thr, tile 256m x 64e, k-tile 32, K=512. Same micro-kernel.
// mode 0/1/2 -> scatter to g_q/g_k/g_v as [n][h][l][d]; mode 3 -> plain out.
// ===========================================================================
#define PJ_SA 260
#define PJ_SB 68
__global__ void __launch_bounds__(128, 2) proj4_kernel(
    const float* __restrict__ X, const float* __restrict__ W,
    const float* __restrict__ bias, const float* __restrict__ rel,
    float scale, int mode, float* __restrict__ outp)
{
    extern __shared__ float sm[];
    float* Xs = sm;                 // [32][260]
    float* Ws = sm + 32 * PJ_SA;    // [32][68]  (natural)
    const float* Xp = (mode == 3) ? (const float*)g_ao : X;

    int tid = threadIdx.x;
    int e0 = blockIdx.x * 64, m0 = blockIdx.y * 256;
    int tx = tid & 7, ty = tid >> 3;
    int rb = ty * 16;
    u64 acc[8][8] = {};

    for (int kt = 0; kt < Ed; kt += 32) {
        __syncthreads();
        // transpose X (256x32 -> Xs[k'][m]); 4 blocks/thread
        #pragma unroll
        for (int u = 0; u < 4; u++) {
            int blk = tid + u * 128;
            int k4 = (blk & 7) * 4, m4 = (blk >> 3) * 4;
            float4 r0 = *(const float4*)(Xp + (size_t)(m0 + m4 + 0) * Ed + kt + k4);
            float4 r1 = *(const float4*)(Xp + (size_t)(m0 + m4 + 1) * Ed + kt + k4);
            float4 r2 = *(const float4*)(Xp + (size_t)(m0 + m4 + 2) * Ed + kt + k4);
            float4 r3 = *(const float4*)(Xp + (size_t)(m0 + m4 + 3) * Ed + kt + k4);
            *(float4*)(Xs + (k4 + 0) * PJ_SA + m4) = make_float4(r0.x, r1.x, r2.x, r3.x);
            *(float4*)(Xs + (k4 + 1) * PJ_SA + m4) = make_float4(r0.y, r1.y, r2.y, r3.y);
            *(float4*)(Xs + (k4 + 2) * PJ_SA + m4) = make_float4(r0.z, r1.z, r2.z, r3.z);
            *(float4*)(Xs + (k4 + 3) * PJ_SA + m4) = make_float4(r0.w, r1.w, r2.w, r3.w);
        }
        // transpose W (64e x 32k -> Ws[k'][e], natural); 128 blocks, 1/thread
        {
            int k4 = (tid & 7) * 4, e4 = (tid >> 3) * 4;
            float4 w0 = *(const float4*)(W + (size_t)(e0 + e4 + 0) * Ed + kt + k4);
            float4 w1 = *(const float4*)(W + (size_t)(e0 + e4 + 1) * Ed + kt + k4);
            float4 w2 = *(const float4*)(W + (size_t)(e0 + e4 + 2) * Ed + kt + k4);
            float4 w3 = *(const float4*)(W + (size_t)(e0 + e4 + 3) * Ed + kt + k4);
            *(float4*)(Ws + (k4 + 0) * PJ_SB + e4) = make_float4(w0.x, w1.x, w2.x, w3.x);
            *(float4*)(Ws + (k4 + 1) * PJ_SB + e4) = make_float4(w0.y, w1.y, w2.y, w3.y);
            *(float4*)(Ws + (k4 + 2) * PJ_SB + e4) = make_float4(w0.z, w1.z, w2.z, w3.z);
            *(float4*)(Ws + (k4 + 3) * PJ_SB + e4) = make_float4(w0.w, w1.w, w2.w, w3.w);
        }
        __syncthreads();

        #pragma unroll 4
        for (int k = 0; k < 32; k++) {
            const ulonglong2* Ad = (const ulonglong2*)(Xs + k * PJ_SA + rb);
            u64 a[8], bb[8];
            ulonglong2 t;
            t = Ad[0]; a[0] = t.x; a[1] = t.y;
            t = Ad[1]; a[2] = t.x; a[3] = t.y;
            t = Ad[2]; a[4] = t.x; a[5] = t.y;
            t = Ad[3]; a[6] = t.x; a[7] = t.y;
            const float4* Bf = (const float4*)(Ws + k * PJ_SB + tx * 8);
            float4 b0 = Bf[0], b1 = Bf[1];
            bb[0] = dup2(b0.x); bb[1] = dup2(b0.y); bb[2] = dup2(b0.z); bb[3] = dup2(b0.w);
            bb[4] = dup2(b1.x); bb[5] = dup2(b1.y); bb[6] = dup2(b1.z); bb[7] = dup2(b1.w);
            #pragma unroll
            for (int i = 0; i < 8; i++)
                #pragma unroll
                for (int j = 0; j < 8; j++)
                    acc[i][j] = ffma2(a[i], bb[j], acc[i][j]);
        }
    }

    // epilogue: e index = e0 + tx*8 + j
    float bs[8], rl[8];
    #pragma unroll
    for (int j = 0; j < 8; j++) {
        int e = e0 + tx * 8 + j;
        bs[j] = bias[e];
        rl[j] = rel ? rel[e] : 0.f;
    }
    int hh = e0 >> 6;
    float* dst012 = (mode == 0) ? g_q : (mode == 1) ? g_k : g_v;

    #pragma unroll
    for (int i = 0; i < 8; i++) {
        #pragma unroll
        for (int hp = 0; hp < 2; hp++) {
            int m = m0 + rb + 2 * i + hp;
            float v[8];
            #pragma unroll
            for (int j = 0; j < 8; j++) {
                float x = hp ? dhi(acc[i][j]) : dlo(acc[i][j]);
                v[j] = (x + bs[j] + rl[j]) * scale;
            }
            if (mode < 3) {
                int l = m >> 2, nn = m & 3;
                float* base = dst012 + ((size_t)(nn * Hd + hh) * Ld + l) * Dd + tx * 8;
                *(float4*)(base)     = make_float4(v[0], v[1], v[2], v[3]);
                *(float4*)(base + 4) = make_float4(v[4], v[5], v[6], v[7]);
            } else {
                float* base = outp + (size_t)m * Ed + e0 + tx * 8;
                *(float4*)(base)     = make_float4(v[0], v[1], v[2], v[3]);
                *(float4*)(base + 4) = make_float4(v[4], v[5], v[6], v[7]);
            }
        }
    }
}

// ===========================================================================
// Softmax in place over s (per l,n,h) + head-mean -> att_weights
// ===========================================================================
__global__ void __launch_bounds__(256) softmax_kernel(float* __restrict__ attw)
{
    int l = blockIdx.x, n = blockIdx.y;
    int tid = threadIdx.x;
    __shared__ float red[8];
    float mean[8] = {0, 0, 0, 0, 0, 0, 0, 0};

    for (int h = 0; h < Hd; h++) {
        float* row = g_sc + ((size_t)(n * Hd + h) * Ld + l) * Sd;
        float x[8];
        float mx = -1e30f;
        #pragma unroll
        for (int i = 0; i < 8; i++) {
            x[i] = row[tid + (i << 8)];
            mx = fmaxf(mx, x[i]);
        }
        #pragma unroll
        for (int o = 16; o; o >>= 1) mx = fmaxf(mx, __shfl_xor_sync(0xffffffffu, mx, o));
        if ((tid & 31) == 0) red[tid >> 5] = mx;
        __syncthreads();
        if (tid < 32) {
            float w = (tid < 8) ? red[tid] : -1e30f;
            #pragma unroll
            for (int o = 4; o; o >>= 1) w = fmaxf(w, __shfl_xor_sync(0xffffffffu, w, o));
            if (tid == 0) red[0] = w;
        }
        __syncthreads();
        mx = red[0];
        __syncthreads();

        float sum = 0.f;
        #pragma unroll
        for (int i = 0; i < 8; i++) {
            x[i] = __expf(x[i] - mx);
            sum += x[i];
        }
        #pragma unroll
        for (int o = 16; o; o >>= 1) sum += __shfl_xor_sync(0xffffffffu, sum, o);
        if ((tid & 31) == 0) red[tid >> 5] = sum;
        __syncthreads();
        if (tid < 32) {
            float w = (tid < 8) ? red[tid] : 0.f;
            #pragma unroll
            for (int o = 4; o; o >>= 1) w += __shfl_xor_sync(0xffffffffu, w, o);
            if (tid == 0) red[0] = w;
        }
        __syncthreads();
        float inv = 1.0f / red[0];
        __syncthreads();

        #pragma unroll
        for (int i = 0; i < 8; i++) {
            float p = x[i] * inv;
            row[tid + (i << 8)] = p;
            mean[i] += p;
        }
    }

    float* aw = attw + ((size_t)n * Ld + l) * Sd;
    #pragma unroll
    for (int i = 0; i < 8; i++)
        aw[tid + (i << 8)] = mean[i] * 0.125f;
}

// ---------------------------------------------------------------------------
extern "C" void kernel_launch(void* const* d_in, const int* in_sizes, int n_in,
                              void* d_out, int out_size)
{
    const float* query = (const float*)d_in[0];
    const float* key   = (const float*)d_in[1];
    const float* value = (const float*)d_in[2];
    // d_in[3] sin_pos_enc: unused — rel_shift term is constant over the
    // softmax axis in the reference and cancels exactly.
    const float* W     = (const float*)d_in[4];   // (3E, E)
    const float* bias  = (const float*)d_in[5];   // (3E,)
    const float* out_w = (const float*)d_in[6];
    const float* out_b = (const float*)d_in[7];
    // d_in[8] rel_proj_w: unused (cancels)
    const float* rel_u = (const float*)d_in[9];   // (H,D) == E contiguous floats
    // d_in[10] rel_v: unused (cancels)

    float* out  = (float*)d_out;                      // (L, N, E)
    float* attw = out + (size_t)Ld * NBd * Ed;        // (N, L, S)

    const int QK_SMEM = (64 * QK_SA + 64 * QK_SB) * 4;   // 67584 B
    const int PV_SMEM = (32 * PV_SA + 32 * PV_SB) * 4;   // 41984 B
    const int PJ_SMEM = (32 * PJ_SA + 32 * PJ_SB) * 4;   // 41984 B
    cudaFuncSetAttribute(qk4_kernel,   cudaFuncAttributeMaxDynamicSharedMemorySize, QK_SMEM);
    cudaFuncSetAttribute(pv4_kernel,   cudaFuncAttributeMaxDynamicSharedMemorySize, PV_SMEM);
    cudaFuncSetAttribute(proj4_kernel, cudaFuncAttributeMaxDynamicSharedMemorySize, PJ_SMEM);

    dim3 gp(Ed / 64, Md / 256);
    // q_eff = (q + rel_u) / sqrt(D)
    proj4_kernel<<<gp, 128, PJ_SMEM>>>(query, W,               bias,          rel_u,   0.125f, 0, nullptr);
    proj4_kernel<<<gp, 128, PJ_SMEM>>>(key,   W + Ed * Ed,     bias + Ed,     nullptr, 1.0f,   1, nullptr);
    proj4_kernel<<<gp, 128, PJ_SMEM>>>(value, W + 2 * Ed * Ed, bias + 2 * Ed, nullptr, 1.0f,   2, nullptr);

    qk4_kernel<<<dim3(Sd / 128, Ld / 128, BATCHd), 128, QK_SMEM>>>();
    softmax_kernel<<<dim3(Ld, NBd), 256>>>(attw);
    pv4_kernel<<<dim3(Ld / 256, BATCHd), 128, PV_SMEM>>>();

    proj4_kernel<<<gp, 128, PJ_SMEM>>>(nullptr, out_w, out_b, nullptr, 1.0f, 3, out);
}